// round 6
// baseline (speedup 1.0000x reference)
#include <cuda_runtime.h>

// RVQTokenizer encode: x [N,D] f32, codebooks [Q,K,D] f32.
// Output (mode 0): [codes as float (N*Q)] ++ [quantized f32 (N*D)].
//
// Fast path: packed-f32x2 FMA scoring. Near-ties (top-2 gap < MARGIN) are
// re-decided by a full-K rescan bit-replicating the reference (XLA CPU,
// aarch64, fast-math vectorized reduce):
//   norms : 16 strided fused-fmla lanes (k mod 16), linear part fold
//           ((A0+A1)+A2)+A3, shuffle-halves horizontal (c0+c2)+(c1+c3)
//   dot   : sequential ascending fused fmaf chain (Eigen/ACL gebp)
//   d2    : fl( fl(S - 2*dot) + C )
//   argmin: strict <, first index wins
// Residual state bit-exact: q += cb[idx]; r = x - q (fp32 elementwise).

#define NROWS 262144
#define NQ    8
#define NK    1024
#define ND    64

#define TILE_K    128
#define CB_STRIDE 68
#define THREADS   128
#define ROWS_PER_BLOCK (THREADS * 2)
#define MARGIN    2e-3f

__device__ float g_q[(size_t)NROWS * ND];   // q accumulator scratch (64 MB)

union F2U { float2 f; unsigned long long u; };

__device__ __forceinline__ float2 ffma2(float2 a, float2 b, float2 c) {
    F2U A, B, C, D;
    A.f = a; B.f = b; C.f = c;
    asm("fma.rn.f32x2 %0, %1, %2, %3;" : "=l"(D.u) : "l"(A.u), "l"(B.u), "l"(C.u));
    return D.f;
}

// LLVM-vectorized (VF=4, IC=4) strided-lane replica of sum(v*v) over 64:
// lane l accumulates k ≡ l (mod 16) with fused fmaf (ascending);
// parts folded linearly; <4xf32> horizontal = shuffle-halves.
__device__ __forceinline__ float xla_rowsum_sq16(const float* __restrict__ v) {
    float a[16];
#pragma unroll
    for (int l = 0; l < 16; l++) a[l] = 0.0f;
#pragma unroll
    for (int j = 0; j < 4; j++)
#pragma unroll
        for (int l = 0; l < 16; l++) {
            float e = v[16 * j + l];
            a[l] = fmaf(e, e, a[l]);
        }
    float c[4];
#pragma unroll
    for (int l = 0; l < 4; l++) {
        float s = __fadd_rn(a[l], a[l + 4]);       // (A0+A1)
        s = __fadd_rn(s, a[l + 8]);                // +A2
        c[l] = __fadd_rn(s, a[l + 12]);            // +A3  (linear fold)
    }
    float h0 = __fadd_rn(c[0], c[2]);
    float h1 = __fadd_rn(c[1], c[3]);
    return __fadd_rn(h0, h1);
}

// Full-K reference-replica rescan.
__device__ __noinline__ int rescan_row(const float2* __restrict__ r,
                                       const float* __restrict__ cbj)
{
    float rs[ND];
#pragma unroll
    for (int k = 0; k < ND / 2; k++) { rs[2 * k] = r[k].x; rs[2 * k + 1] = r[k].y; }

    float S = xla_rowsum_sq16(rs);

    float best = __int_as_float(0x7f800000);
    int bidx = 0;
    for (int c = 0; c < NK; c++) {
        const float* cp = cbj + (size_t)c * ND;
        float C = xla_rowsum_sq16(cp);
        float acc = 0.0f;
        for (int k = 0; k < ND; k++)
            acc = fmaf(rs[k], cp[k], acc);        // sequential fused dot chain
        float B  = __fmul_rn(2.0f, acc);          // exact
        float t1 = __fadd_rn(S, -B);              // fl(S - B)
        float d2 = __fadd_rn(t1, C);              // fl(t1 + C)
        if (d2 < best) { best = d2; bidx = c; }   // strict <: first-min wins
    }
    return bidx;
}

// mode 0: [codes as float] ++ [quantized]; mode 1: int codes; mode 2: quantized.
__global__ __launch_bounds__(THREADS, 2)
void rvq_kernel(const float* __restrict__ x,
                const float* __restrict__ cb,
                float* __restrict__ out,
                int mode)
{
    __shared__ float sh_cb[TILE_K * CB_STRIDE];
    __shared__ float sh_norm[TILE_K];

    const int t = threadIdx.x;
    const long long row_a = (long long)blockIdx.x * ROWS_PER_BLOCK + t;
    const long long row_b = row_a + THREADS;

    float2 ra[ND / 2], rb[ND / 2];
    {
        const float4* xa4 = (const float4*)(x + row_a * ND);
        const float4* xb4 = (const float4*)(x + row_b * ND);
#pragma unroll
        for (int i = 0; i < ND / 4; i++) {
            float4 va = xa4[i];
            ra[2 * i]     = make_float2(va.x, va.y);
            ra[2 * i + 1] = make_float2(va.z, va.w);
            float4 vb = xb4[i];
            rb[2 * i]     = make_float2(vb.x, vb.y);
            rb[2 * i + 1] = make_float2(vb.z, vb.w);
        }
    }

    float* outq = (mode == 0) ? (out + (size_t)NROWS * NQ)
                              : ((mode == 2) ? out : nullptr);

    for (int j = 0; j < NQ; j++) {
        const float INF = __int_as_float(0x7f800000);
        float best_a = INF, sec_a = INF, best_b = INF, sec_b = INF;
        int bia = 0, bib = 0;
        const float* cbj = cb + (size_t)j * NK * ND;

        for (int tile = 0; tile < NK / TILE_K; ++tile) {
            __syncthreads();
            const float4* src = (const float4*)(cbj + (size_t)tile * TILE_K * ND);
#pragma unroll
            for (int it = 0; it < (TILE_K * ND / 4) / THREADS; ++it) {  // 16
                int idx  = it * THREADS + t;
                int code = idx >> 4;
                int d4   = idx & 15;
                float4 v = src[idx];
                *(float4*)&sh_cb[code * CB_STRIDE + d4 * 4] = v;
            }
            __syncthreads();
            {   // fast per-code norm (fast-path ordering only)
                float s = 0.f;
                const float* cp = &sh_cb[t * CB_STRIDE];
#pragma unroll
                for (int d = 0; d < ND; d++) s = fmaf(cp[d], cp[d], s);
                sh_norm[t] = s;
            }
            __syncthreads();

            for (int c = 0; c < TILE_K; c++) {
                const float2* cp = (const float2*)&sh_cb[c * CB_STRIDE];
                float2 aa = make_float2(0.f, 0.f);
                float2 ab = make_float2(0.f, 0.f);
#pragma unroll
                for (int d = 0; d < ND / 2; d++) {
                    float2 cv = cp[d];
                    aa = ffma2(ra[d], cv, aa);
                    ab = ffma2(rb[d], cv, ab);
                }
                float nrm = sh_norm[c];
                float da = nrm - 2.f * (aa.x + aa.y);
                float db = nrm - 2.f * (ab.x + ab.y);
                int ci = tile * TILE_K + c;
                if (da < best_a)      { sec_a = best_a; best_a = da; bia = ci; }
                else if (da < sec_a)  { sec_a = da; }
                if (db < best_b)      { sec_b = best_b; best_b = db; bib = ci; }
                else if (db < sec_b)  { sec_b = db; }
            }
        }

        // Near-tie: full-K reference-replica rescan.
        if (sec_a - best_a < MARGIN) bia = rescan_row(ra, cbj);
        if (sec_b - best_b < MARGIN) bib = rescan_row(rb, cbj);

        // Bit-exact reference state update: q += cb[idx]; r = x - q.
        {
            const float4* ca  = (const float4*)(cbj + (size_t)bia * ND);
            const float4* cbv = (const float4*)(cbj + (size_t)bib * ND);
            float4* qa = (float4*)(g_q + row_a * ND);
            float4* qb = (float4*)(g_q + row_b * ND);
            const float4* xa4 = (const float4*)(x + row_a * ND);
            const float4* xb4 = (const float4*)(x + row_b * ND);
#pragma unroll
            for (int i = 0; i < ND / 4; i++) {
                float4 c4 = ca[i];
                float4 q4;
                if (j == 0) q4 = c4;
                else { float4 qo = qa[i];
                       q4 = make_float4(__fadd_rn(qo.x, c4.x), __fadd_rn(qo.y, c4.y),
                                        __fadd_rn(qo.z, c4.z), __fadd_rn(qo.w, c4.w)); }
                qa[i] = q4;
                float4 x4 = xa4[i];
                ra[2 * i]     = make_float2(__fadd_rn(x4.x, -q4.x), __fadd_rn(x4.y, -q4.y));
                ra[2 * i + 1] = make_float2(__fadd_rn(x4.z, -q4.z), __fadd_rn(x4.w, -q4.w));
                if (j == NQ - 1 && outq) ((float4*)(outq + row_a * ND))[i] = q4;

                float4 d4 = cbv[i];
                float4 p4;
                if (j == 0) p4 = d4;
                else { float4 qo = qb[i];
                       p4 = make_float4(__fadd_rn(qo.x, d4.x), __fadd_rn(qo.y, d4.y),
                                        __fadd_rn(qo.z, d4.z), __fadd_rn(qo.w, d4.w)); }
                qb[i] = p4;
                float4 y4 = xb4[i];
                rb[2 * i]     = make_float2(__fadd_rn(y4.x, -p4.x), __fadd_rn(y4.y, -p4.y));
                rb[2 * i + 1] = make_float2(__fadd_rn(y4.z, -p4.z), __fadd_rn(y4.w, -p4.w));
                if (j == NQ - 1 && outq) ((float4*)(outq + row_b * ND))[i] = p4;
            }
        }

        if (mode == 0) {
            out[row_a * NQ + j] = (float)bia;
            out[row_b * NQ + j] = (float)bib;
        } else if (mode == 1) {
            ((int*)out)[row_a * NQ + j] = bia;
            ((int*)out)[row_b * NQ + j] = bib;
        }
    }
}

extern "C" void kernel_launch(void* const* d_in, const int* in_sizes, int n_in,
                              void* d_out, int out_size)
{
    const float* x  = (const float*)d_in[0];
    const float* cb = (const float*)d_in[1];
    if (n_in >= 2 && in_sizes[0] == NQ * NK * ND && in_sizes[1] == NROWS * ND) {
        cb = (const float*)d_in[0];
        x  = (const float*)d_in[1];
    }

    int mode = 0;
    if (out_size == NROWS * NQ)      mode = 1;
    else if (out_size == NROWS * ND) mode = 2;

    rvq_kernel<<<NROWS / ROWS_PER_BLOCK, THREADS>>>(x, cb, (float*)d_out, mode);
}

// round 7
// speedup vs baseline: 1.1920x; 1.1920x over previous
#include <cuda_runtime.h>

// RVQTokenizer encode: x [N,D] f32, codebooks [Q,K,D] f32.
// Output (mode 0): [codes as float (N*Q)] ++ [quantized f32 (N*D)].
//
// PROVEN bit-exact vs reference (R6, rel_err = 0.0):
//   norms : 16 strided fused-fmaf lanes (k mod 16), linear part fold
//           ((A0+A1)+A2)+A3, shuffle-halves horizontal (c0+c2)+(c1+c3)
//   dot   : sequential ascending fused fmaf chain
//   d2    : fl( fl(S - 2*dot) + C ); argmin strict <, first index wins
//   state : q += cb[idx]; r = x - q (fp32 elementwise, __fadd_rn)
// DO NOT change that arithmetic. This round only restructures for speed:
//   - rescan reads residual from global x/g_q (ra/rb dead across call)
//   - __launch_bounds__(128,3): 170-reg cap -> 3 CTAs/SM (was 255/2)
//   - 2-code unrolled scoring: 4 independent FFMA2 chains per thread

#define NROWS 262144
#define NQ    8
#define NK    1024
#define ND    64

#define TILE_K    128
#define CB_STRIDE 68
#define THREADS   128
#define ROWS_PER_BLOCK (THREADS * 2)
#define MARGIN    2e-3f

__device__ float g_q[(size_t)NROWS * ND];   // q accumulator scratch (64 MB)

union F2U { float2 f; unsigned long long u; };

__device__ __forceinline__ float2 ffma2(float2 a, float2 b, float2 c) {
    F2U A, B, C, D;
    A.f = a; B.f = b; C.f = c;
    asm("fma.rn.f32x2 %0, %1, %2, %3;" : "=l"(D.u) : "l"(A.u), "l"(B.u), "l"(C.u));
    return D.f;
}

// Reference norm replica (PROVEN): LLVM VF=4 IC=4 strided lanes over 64 elems.
__device__ __forceinline__ float xla_rowsum_sq16(const float* __restrict__ v) {
    float a[16];
#pragma unroll
    for (int l = 0; l < 16; l++) a[l] = 0.0f;
#pragma unroll
    for (int j = 0; j < 4; j++)
#pragma unroll
        for (int l = 0; l < 16; l++) {
            float e = v[16 * j + l];
            a[l] = fmaf(e, e, a[l]);
        }
    float c[4];
#pragma unroll
    for (int l = 0; l < 4; l++) {
        float s = __fadd_rn(a[l], a[l + 4]);
        s = __fadd_rn(s, a[l + 8]);
        c[l] = __fadd_rn(s, a[l + 12]);
    }
    float h0 = __fadd_rn(c[0], c[2]);
    float h1 = __fadd_rn(c[1], c[3]);
    return __fadd_rn(h0, h1);
}

// Full-K reference-replica rescan. Residual re-derived from global x and g_q
// with the exact same ops that produced the in-register copy (bit-identical).
__device__ __noinline__ int rescan_row_g(const float* __restrict__ x,
                                         int use_q, long long row,
                                         const float* __restrict__ cbj)
{
    const float* xr = x + row * ND;
    const float* qr = g_q + row * ND;
    float rs[ND];
#pragma unroll
    for (int k = 0; k < ND; k++)
        rs[k] = use_q ? __fadd_rn(xr[k], -qr[k]) : xr[k];

    float S = xla_rowsum_sq16(rs);

    float best = __int_as_float(0x7f800000);
    int bidx = 0;
    for (int c = 0; c < NK; c++) {
        const float* cp = cbj + (size_t)c * ND;
        float C = xla_rowsum_sq16(cp);
        float acc = 0.0f;
        for (int k = 0; k < ND; k++)
            acc = fmaf(rs[k], cp[k], acc);        // sequential fused dot chain
        float B  = __fmul_rn(2.0f, acc);
        float t1 = __fadd_rn(S, -B);
        float d2 = __fadd_rn(t1, C);
        if (d2 < best) { best = d2; bidx = c; }   // strict <: first-min wins
    }
    return bidx;
}

// mode 0: [codes as float] ++ [quantized]; mode 1: int codes; mode 2: quantized.
__global__ __launch_bounds__(THREADS, 3)
void rvq_kernel(const float* __restrict__ x,
                const float* __restrict__ cb,
                float* __restrict__ out,
                int mode)
{
    __shared__ float sh_cb[TILE_K * CB_STRIDE];
    __shared__ float sh_norm[TILE_K];

    const int t = threadIdx.x;
    const long long row_a = (long long)blockIdx.x * ROWS_PER_BLOCK + t;
    const long long row_b = row_a + THREADS;

    float2 ra[ND / 2], rb[ND / 2];
    {
        const float4* xa4 = (const float4*)(x + row_a * ND);
        const float4* xb4 = (const float4*)(x + row_b * ND);
#pragma unroll
        for (int i = 0; i < ND / 4; i++) {
            float4 va = xa4[i];
            ra[2 * i]     = make_float2(va.x, va.y);
            ra[2 * i + 1] = make_float2(va.z, va.w);
            float4 vb = xb4[i];
            rb[2 * i]     = make_float2(vb.x, vb.y);
            rb[2 * i + 1] = make_float2(vb.z, vb.w);
        }
    }

    float* outq = (mode == 0) ? (out + (size_t)NROWS * NQ)
                              : ((mode == 2) ? out : nullptr);

    for (int j = 0; j < NQ; j++) {
        const float INF = __int_as_float(0x7f800000);
        float best_a = INF, sec_a = INF, best_b = INF, sec_b = INF;
        int bia = 0, bib = 0;
        const float* cbj = cb + (size_t)j * NK * ND;

        for (int tile = 0; tile < NK / TILE_K; ++tile) {
            __syncthreads();
            const float4* src = (const float4*)(cbj + (size_t)tile * TILE_K * ND);
#pragma unroll
            for (int it = 0; it < (TILE_K * ND / 4) / THREADS; ++it) {  // 16
                int idx  = it * THREADS + t;
                int code = idx >> 4;
                int d4   = idx & 15;
                float4 v = src[idx];
                *(float4*)&sh_cb[code * CB_STRIDE + d4 * 4] = v;
            }
            __syncthreads();
            {   // fast per-code norm (fast-path ordering only)
                float s = 0.f;
                const float* cp = &sh_cb[t * CB_STRIDE];
#pragma unroll
                for (int d = 0; d < ND; d++) s = fmaf(cp[d], cp[d], s);
                sh_norm[t] = s;
            }
            __syncthreads();

            // 2 codes x 2 rows: 4 independent FFMA2 chains, broadcast LDS.
            for (int c = 0; c < TILE_K; c += 2) {
                const float2* cp0 = (const float2*)&sh_cb[c * CB_STRIDE];
                const float2* cp1 = (const float2*)&sh_cb[(c + 1) * CB_STRIDE];
                float2 a0 = make_float2(0.f, 0.f), a1 = a0;
                float2 b0 = a0, b1 = a0;
#pragma unroll
                for (int d = 0; d < ND / 2; d++) {
                    float2 cv0 = cp0[d];
                    float2 cv1 = cp1[d];
                    a0 = ffma2(ra[d], cv0, a0);
                    b0 = ffma2(rb[d], cv0, b0);
                    a1 = ffma2(ra[d], cv1, a1);
                    b1 = ffma2(rb[d], cv1, b1);
                }
                float n0 = sh_norm[c], n1 = sh_norm[c + 1];
                float da0 = n0 - 2.f * (a0.x + a0.y);
                float db0 = n0 - 2.f * (b0.x + b0.y);
                float da1 = n1 - 2.f * (a1.x + a1.y);
                float db1 = n1 - 2.f * (b1.x + b1.y);
                int ci = tile * TILE_K + c;
                if (da0 < best_a)      { sec_a = best_a; best_a = da0; bia = ci; }
                else if (da0 < sec_a)  { sec_a = da0; }
                if (da1 < best_a)      { sec_a = best_a; best_a = da1; bia = ci + 1; }
                else if (da1 < sec_a)  { sec_a = da1; }
                if (db0 < best_b)      { sec_b = best_b; best_b = db0; bib = ci; }
                else if (db0 < sec_b)  { sec_b = db0; }
                if (db1 < best_b)      { sec_b = best_b; best_b = db1; bib = ci + 1; }
                else if (db1 < sec_b)  { sec_b = db1; }
            }
        }

        // Near-tie: full-K reference-replica rescan (reads state from global;
        // ra/rb are dead here — update below recomputes them from x and g_q).
        if (sec_a - best_a < MARGIN) bia = rescan_row_g(x, j > 0, row_a, cbj);
        if (sec_b - best_b < MARGIN) bib = rescan_row_g(x, j > 0, row_b, cbj);

        // Bit-exact reference state update: q += cb[idx]; r = x - q.
        {
            const float4* ca  = (const float4*)(cbj + (size_t)bia * ND);
            const float4* cbv = (const float4*)(cbj + (size_t)bib * ND);
            float4* qa = (float4*)(g_q + row_a * ND);
            float4* qb = (float4*)(g_q + row_b * ND);
            const float4* xa4 = (const float4*)(x + row_a * ND);
            const float4* xb4 = (const float4*)(x + row_b * ND);
#pragma unroll
            for (int i = 0; i < ND / 4; i++) {
                float4 c4 = ca[i];
                float4 q4;
                if (j == 0) q4 = c4;
                else { float4 qo = qa[i];
                       q4 = make_float4(__fadd_rn(qo.x, c4.x), __fadd_rn(qo.y, c4.y),
                                        __fadd_rn(qo.z, c4.z), __fadd_rn(qo.w, c4.w)); }
                qa[i] = q4;
                float4 x4 = xa4[i];
                ra[2 * i]     = make_float2(__fadd_rn(x4.x, -q4.x), __fadd_rn(x4.y, -q4.y));
                ra[2 * i + 1] = make_float2(__fadd_rn(x4.z, -q4.z), __fadd_rn(x4.w, -q4.w));
                if (j == NQ - 1 && outq) ((float4*)(outq + row_a * ND))[i] = q4;

                float4 d4 = cbv[i];
                float4 p4;
                if (j == 0) p4 = d4;
                else { float4 qo = qb[i];
                       p4 = make_float4(__fadd_rn(qo.x, d4.x), __fadd_rn(qo.y, d4.y),
                                        __fadd_rn(qo.z, d4.z), __fadd_rn(qo.w, d4.w)); }
                qb[i] = p4;
                float4 y4 = xb4[i];
                rb[2 * i]     = make_float2(__fadd_rn(y4.x, -p4.x), __fadd_rn(y4.y, -p4.y));
                rb[2 * i + 1] = make_float2(__fadd_rn(y4.z, -p4.z), __fadd_rn(y4.w, -p4.w));
                if (j == NQ - 1 && outq) ((float4*)(outq + row_b * ND))[i] = p4;
            }
        }

        if (mode == 0) {
            out[row_a * NQ + j] = (float)bia;
            out[row_b * NQ + j] = (float)bib;
        } else if (mode == 1) {
            ((int*)out)[row_a * NQ + j] = bia;
            ((int*)out)[row_b * NQ + j] = bib;
        }
    }
}

extern "C" void kernel_launch(void* const* d_in, const int* in_sizes, int n_in,
                              void* d_out, int out_size)
{
    const float* x  = (const float*)d_in[0];
    const float* cb = (const float*)d_in[1];
    if (n_in >= 2 && in_sizes[0] == NQ * NK * ND && in_sizes[1] == NROWS * ND) {
        cb = (const float*)d_in[0];
        x  = (const float*)d_in[1];
    }

    int mode = 0;
    if (out_size == NROWS * NQ)      mode = 1;
    else if (out_size == NROWS * ND) mode = 2;

    rvq_kernel<<<NROWS / ROWS_PER_BLOCK, THREADS>>>(x, cb, (float*)d_out, mode);
}